// round 5
// baseline (speedup 1.0000x reference)
#include <cuda_runtime.h>
#include <cuda_fp16.h>
#include <cstdint>

// out[B,N] = x[B,K] @ w[K,N] + bias[N]
// fp16 HMMA m16n8k16 f32-accum. CTA tile 128x256, warp tile 64x64 (8 warps).
#define BATCH 4096
#define KDIM  4096
#define NDIM  4096

#define TM 128
#define TN 256
#define KC 64          // K elements per stage (128 bytes fp16 per row)
#define STAGES 3
#define THREADS 256    // 8 warps: 2 (M) x 4 (N), warp tile 64x64
#define K_ITERS (KDIM / KC)   // 64

// ---------------- scratch (device globals: allocation-free) ----------------
__device__ __half g_x[(size_t)BATCH * KDIM];
__device__ __half g_w[(size_t)NDIM * KDIM];   // transposed: [n][k]

// SMEM stage: A tile 128 rows x 128B, B tile 256 rows x 128B
#define STAGE_BYTES ((TM + TN) * 128)       // 49152
#define SMEM_TOTAL  (STAGES * STAGE_BYTES)  // 147456 (1 CTA/SM)

__device__ __forceinline__ uint32_t smem_u32(const void* p) {
    uint32_t a;
    asm("{ .reg .u64 t; cvta.to.shared.u64 t, %1; cvt.u32.u64 %0, t; }"
        : "=r"(a) : "l"(p));
    return a;
}

__device__ __forceinline__ void cp_async16(uint32_t smaddr, const void* gptr) {
    asm volatile("cp.async.cg.shared.global [%0], [%1], 16;\n"
                 :: "r"(smaddr), "l"(gptr));
}
#define CP_COMMIT() asm volatile("cp.async.commit_group;\n" ::: "memory")
#define CP_WAIT1()  asm volatile("cp.async.wait_group 1;\n" ::: "memory")

__device__ __forceinline__ void ldsm_x4(uint32_t addr, uint32_t& r0, uint32_t& r1,
                                        uint32_t& r2, uint32_t& r3) {
    asm volatile("ldmatrix.sync.aligned.m8n8.x4.shared.b16 {%0,%1,%2,%3}, [%4];"
                 : "=r"(r0), "=r"(r1), "=r"(r2), "=r"(r3) : "r"(addr));
}

__device__ __forceinline__ void mma_16816(float* c, const uint32_t* a,
                                          uint32_t b0, uint32_t b1) {
    asm volatile(
        "mma.sync.aligned.m16n8k16.row.col.f32.f16.f16.f32 "
        "{%0,%1,%2,%3}, {%4,%5,%6,%7}, {%8,%9}, {%0,%1,%2,%3};"
        : "+f"(c[0]), "+f"(c[1]), "+f"(c[2]), "+f"(c[3])
        : "r"(a[0]), "r"(a[1]), "r"(a[2]), "r"(a[3]), "r"(b0), "r"(b1));
}

// ---------------- prepass 1: convert x -> fp16 ----------------
__global__ void __launch_bounds__(256) conv_x_kernel(const float4* __restrict__ x) {
    size_t i = (size_t)blockIdx.x * blockDim.x + threadIdx.x;  // 4 floats / thread
    float4 v = x[i];
    __half2* xp = reinterpret_cast<__half2*>(g_x);
    xp[2 * i]     = __floats2half2_rn(v.x, v.y);
    xp[2 * i + 1] = __floats2half2_rn(v.z, v.w);
}

// ---------------- prepass 2: transpose + convert w -> [n][k] fp16 ----------
__global__ void __launch_bounds__(256) conv_transpose_w_kernel(const float* __restrict__ w) {
    __shared__ float tile[32][33];
    int o0 = blockIdx.x * 32;  // output (N) tile
    int i0 = blockIdx.y * 32;  // input (K) tile
    int tx = threadIdx.x, ty = threadIdx.y;
    #pragma unroll
    for (int r = ty; r < 32; r += 8)
        tile[r][tx] = w[(size_t)(i0 + r) * NDIM + o0 + tx];
    __syncthreads();
    #pragma unroll
    for (int r = ty; r < 32; r += 8) {
        float f = tile[tx][r];  // = w[i0+tx][o0+r]
        g_w[(size_t)(o0 + r) * KDIM + i0 + tx] = __float2half_rn(f);
    }
}

// ---------------- producer helpers ----------------
// 384 rows x 8 segs = 3072 cp.async per stage; 12 per thread (j = 0..11)
__device__ __forceinline__ void load_part(uint32_t sa, int k0, int m0, int n0,
                                          int tid, int j0, int j1) {
    uint32_t sbB = sa + TM * 128;
    #pragma unroll
    for (int j = j0; j < j1; ++j) {
        int t = tid + j * THREADS;
        int row = t >> 3;
        int seg = t & 7;
        if (row < TM) {
            const __half* gp = g_x + (size_t)(m0 + row) * KDIM + k0 + seg * 8;
            uint32_t sm = sa + row * 128 + ((seg ^ (row & 7)) << 4);
            cp_async16(sm, gp);
        } else {
            int rb = row - TM;
            const __half* gp = g_w + (size_t)(n0 + rb) * KDIM + k0 + seg * 8;
            uint32_t sm = sbB + rb * 128 + ((seg ^ (rb & 7)) << 4);
            cp_async16(sm, gp);
        }
    }
}

// ---------------- main GEMM ----------------
__global__ void __launch_bounds__(THREADS, 1)
gemm_fp16_kernel(const float* __restrict__ bias, float* __restrict__ out) {
    extern __shared__ char smem[];
    uint32_t sb = smem_u32(smem);
    int tid = threadIdx.x;
    int lane = tid & 31;
    int wid = tid >> 5;
    int wm = wid & 1;       // M warp group: 64 rows
    int wn = wid >> 1;      // N warp group: 64 cols
    int m0 = blockIdx.y * TM;
    int n0 = blockIdx.x * TN;

    float acc[4][8][4];     // [mt m16 tile][nb n8 tile][c0..c3]
    #pragma unroll
    for (int i = 0; i < 4; ++i)
        #pragma unroll
        for (int j = 0; j < 8; ++j)
            #pragma unroll
            for (int k = 0; k < 4; ++k) acc[i][j][k] = 0.f;

    // prologue: stages 0 and 1
    load_part(sb + 0 * STAGE_BYTES, 0 * KC, m0, n0, tid, 0, 12); CP_COMMIT();
    load_part(sb + 1 * STAGE_BYTES, 1 * KC, m0, n0, tid, 0, 12); CP_COMMIT();

    int la = (lane & 15);
    int khalf = lane >> 4;

    int cons = 0, prod = 2;   // stage indices
    for (int it = 0; it < K_ITERS; ++it) {
        CP_WAIT1();
        __syncthreads();

        uint32_t sa = sb + cons * STAGE_BYTES;
        uint32_t sB = sa + TM * 128;
        uint32_t sp = sb + prod * STAGE_BYTES;
        bool do_load = (it + 2 < K_ITERS);
        int kp = (it + 2) * KC;

        #pragma unroll
        for (int ks = 0; ks < 4; ++ks) {
            // spread producer cp.async: 3 per thread per ks
            if (do_load) load_part(sp, kp, m0, n0, tid, ks * 3, ks * 3 + 3);

            int seg = 2 * ks + khalf;
            // B fragments first: 4 x4 loads cover 8 n8 tiles
            uint32_t bf[8][2];
            #pragma unroll
            for (int q = 0; q < 4; ++q) {
                int row = wn * 64 + q * 16 + la;
                uint32_t addr = sB + row * 128 + ((seg ^ (row & 7)) << 4);
                uint32_t r0, r1, r2, r3;
                ldsm_x4(addr, r0, r1, r2, r3);
                bf[2 * q][0] = r0;     bf[2 * q][1] = r2;
                bf[2 * q + 1][0] = r1; bf[2 * q + 1][1] = r3;
            }
            // per mt: load its A frag, then immediately issue its 8 MMAs
            #pragma unroll
            for (int mt = 0; mt < 4; ++mt) {
                int row = wm * 64 + mt * 16 + la;
                uint32_t addr = sa + row * 128 + ((seg ^ (row & 7)) << 4);
                uint32_t af[4];
                ldsm_x4(addr, af[0], af[1], af[2], af[3]);
                #pragma unroll
                for (int nb = 0; nb < 8; ++nb)
                    mma_16816(acc[mt][nb], af, bf[nb][0], bf[nb][1]);
            }
        }
        CP_COMMIT();

        cons = (cons == STAGES - 1) ? 0 : cons + 1;
        prod = (prod == STAGES - 1) ? 0 : prod + 1;
    }

    // ---------------- epilogue: bias + store ----------------
    float2 bv[8];
    #pragma unroll
    for (int nb = 0; nb < 8; ++nb) {
        int col = n0 + wn * 64 + nb * 8 + (lane & 3) * 2;
        bv[nb] = *reinterpret_cast<const float2*>(bias + col);
    }
    #pragma unroll
    for (int mt = 0; mt < 4; ++mt) {
        int gr = m0 + wm * 64 + mt * 16 + (lane >> 2);
        float* r0p = out + (size_t)gr * NDIM;
        float* r1p = r0p + 8 * (size_t)NDIM;
        #pragma unroll
        for (int nb = 0; nb < 8; ++nb) {
            int col = n0 + wn * 64 + nb * 8 + (lane & 3) * 2;
            float2 v0 = make_float2(acc[mt][nb][0] + bv[nb].x,
                                    acc[mt][nb][1] + bv[nb].y);
            float2 v1 = make_float2(acc[mt][nb][2] + bv[nb].x,
                                    acc[mt][nb][3] + bv[nb].y);
            *reinterpret_cast<float2*>(r0p + col) = v0;
            *reinterpret_cast<float2*>(r1p + col) = v1;
        }
    }
}

// ---------------- launch ----------------
extern "C" void kernel_launch(void* const* d_in, const int* in_sizes, int n_in,
                              void* d_out, int out_size) {
    const float* x    = (const float*)d_in[0];
    const float* w    = (const float*)d_in[1];
    const float* bias = (const float*)d_in[2];
    float* out = (float*)d_out;

    conv_x_kernel<<<(BATCH * (size_t)KDIM / 4) / 256, 256>>>((const float4*)x);
    conv_transpose_w_kernel<<<dim3(NDIM / 32, KDIM / 32), dim3(32, 8)>>>(w);

    cudaFuncSetAttribute(gemm_fp16_kernel,
                         cudaFuncAttributeMaxDynamicSharedMemorySize, SMEM_TOTAL);
    gemm_fp16_kernel<<<dim3(NDIM / TN, BATCH / TM), THREADS, SMEM_TOTAL>>>(bias, out);
}

// round 6
// speedup vs baseline: 1.1108x; 1.1108x over previous
#include <cuda_runtime.h>
#include <cuda_fp16.h>
#include <cstdint>

// out[B,N] = x[B,K] @ w[K,N] + bias[N]
// fp16 HMMA m16n8k16 f32-accum. CTA 128x128, 4 warps (2x2), warp tile 64x64,
// 2 CTAs/SM resident.
#define BATCH 4096
#define KDIM  4096
#define NDIM  4096

#define TM 128
#define TN 128
#define KC 64          // K elements per stage (128 bytes fp16 per row)
#define STAGES 3
#define THREADS 128    // 4 warps: 2 (M) x 2 (N), warp tile 64x64
#define K_ITERS (KDIM / KC)   // 64

// ---------------- scratch (device globals: allocation-free) ----------------
__device__ __half g_x[(size_t)BATCH * KDIM];
__device__ __half g_w[(size_t)NDIM * KDIM];   // transposed: [n][k]

// SMEM stage: A tile 128 rows x 128B, B tile 128 rows x 128B
#define STAGE_BYTES ((TM + TN) * 128)       // 32768
#define SMEM_TOTAL  (STAGES * STAGE_BYTES)  // 98304 (x2 CTAs = 192KB/SM)

__device__ __forceinline__ uint32_t smem_u32(const void* p) {
    uint32_t a;
    asm("{ .reg .u64 t; cvta.to.shared.u64 t, %1; cvt.u32.u64 %0, t; }"
        : "=r"(a) : "l"(p));
    return a;
}

__device__ __forceinline__ void cp_async16(uint32_t smaddr, const void* gptr) {
    asm volatile("cp.async.cg.shared.global [%0], [%1], 16;\n"
                 :: "r"(smaddr), "l"(gptr));
}
#define CP_COMMIT() asm volatile("cp.async.commit_group;\n" ::: "memory")
#define CP_WAIT1()  asm volatile("cp.async.wait_group 1;\n" ::: "memory")

__device__ __forceinline__ void ldsm_x4(uint32_t addr, uint32_t& r0, uint32_t& r1,
                                        uint32_t& r2, uint32_t& r3) {
    asm volatile("ldmatrix.sync.aligned.m8n8.x4.shared.b16 {%0,%1,%2,%3}, [%4];"
                 : "=r"(r0), "=r"(r1), "=r"(r2), "=r"(r3) : "r"(addr));
}

__device__ __forceinline__ void mma_16816(float* c, const uint32_t* a,
                                          uint32_t b0, uint32_t b1) {
    asm volatile(
        "mma.sync.aligned.m16n8k16.row.col.f32.f16.f16.f32 "
        "{%0,%1,%2,%3}, {%4,%5,%6,%7}, {%8,%9}, {%0,%1,%2,%3};"
        : "+f"(c[0]), "+f"(c[1]), "+f"(c[2]), "+f"(c[3])
        : "r"(a[0]), "r"(a[1]), "r"(a[2]), "r"(a[3]), "r"(b0), "r"(b1));
}

// ---------------- prepass 1: convert x -> fp16 ----------------
__global__ void __launch_bounds__(256) conv_x_kernel(const float4* __restrict__ x) {
    size_t i = (size_t)blockIdx.x * blockDim.x + threadIdx.x;  // 4 floats / thread
    float4 v = x[i];
    __half2* xp = reinterpret_cast<__half2*>(g_x);
    xp[2 * i]     = __floats2half2_rn(v.x, v.y);
    xp[2 * i + 1] = __floats2half2_rn(v.z, v.w);
}

// ---------------- prepass 2: transpose + convert w -> [n][k] fp16 ----------
__global__ void __launch_bounds__(256) conv_transpose_w_kernel(const float* __restrict__ w) {
    __shared__ float tile[32][33];
    int o0 = blockIdx.x * 32;  // output (N) tile
    int i0 = blockIdx.y * 32;  // input (K) tile
    int tx = threadIdx.x, ty = threadIdx.y;
    #pragma unroll
    for (int r = ty; r < 32; r += 8)
        tile[r][tx] = w[(size_t)(i0 + r) * NDIM + o0 + tx];
    __syncthreads();
    #pragma unroll
    for (int r = ty; r < 32; r += 8) {
        float f = tile[tx][r];  // = w[i0+tx][o0+r]
        g_w[(size_t)(o0 + r) * KDIM + i0 + tx] = __float2half_rn(f);
    }
}

// ---------------- producer: partial stage fill ----------------
// 256 rows x 8 segs = 2048 cp.async per stage; 16 per thread (j = 0..15)
__device__ __forceinline__ void load_part(uint32_t sa, int k0, int m0, int n0,
                                          int tid, int j0, int j1) {
    uint32_t sbB = sa + TM * 128;
    #pragma unroll
    for (int j = j0; j < j1; ++j) {
        int t = tid + j * THREADS;
        int row = t >> 3;
        int seg = t & 7;
        if (row < TM) {
            const __half* gp = g_x + (size_t)(m0 + row) * KDIM + k0 + seg * 8;
            uint32_t sm = sa + row * 128 + ((seg ^ (row & 7)) << 4);
            cp_async16(sm, gp);
        } else {
            int rb = row - TM;
            const __half* gp = g_w + (size_t)(n0 + rb) * KDIM + k0 + seg * 8;
            uint32_t sm = sbB + rb * 128 + ((seg ^ (rb & 7)) << 4);
            cp_async16(sm, gp);
        }
    }
}

// ---------------- main GEMM ----------------
__global__ void __launch_bounds__(THREADS, 2)
gemm_fp16_kernel(const float* __restrict__ bias, float* __restrict__ out) {
    extern __shared__ char smem[];
    uint32_t sb = smem_u32(smem);
    int tid = threadIdx.x;
    int lane = tid & 31;
    int wid = tid >> 5;
    int wm = wid & 1;       // M warp group: 64 rows
    int wn = wid >> 1;      // N warp group: 64 cols
    int m0 = blockIdx.y * TM;
    int n0 = blockIdx.x * TN;

    float acc[4][8][4];     // [mt m16 tile][nb n8 tile][c0..c3]
    #pragma unroll
    for (int i = 0; i < 4; ++i)
        #pragma unroll
        for (int j = 0; j < 8; ++j)
            #pragma unroll
            for (int k = 0; k < 4; ++k) acc[i][j][k] = 0.f;

    // prologue: stages 0 and 1
    load_part(sb + 0 * STAGE_BYTES, 0 * KC, m0, n0, tid, 0, 16); CP_COMMIT();
    load_part(sb + 1 * STAGE_BYTES, 1 * KC, m0, n0, tid, 0, 16); CP_COMMIT();

    int la = (lane & 15);
    int khalf = lane >> 4;

    int cons = 0, prod = 2;   // stage indices
    for (int it = 0; it < K_ITERS; ++it) {
        CP_WAIT1();
        __syncthreads();

        uint32_t sa = sb + cons * STAGE_BYTES;
        uint32_t sB = sa + TM * 128;
        uint32_t sp = sb + prod * STAGE_BYTES;
        bool do_load = (it + 2 < K_ITERS);
        int kp = (it + 2) * KC;

        #pragma unroll
        for (int ks = 0; ks < 4; ++ks) {
            // spread producer cp.async: 4 per thread per ks
            if (do_load) load_part(sp, kp, m0, n0, tid, ks * 4, ks * 4 + 4);

            int seg = 2 * ks + khalf;
            // B fragments first: 4 x4 loads cover 8 n8 tiles
            uint32_t bf[8][2];
            #pragma unroll
            for (int q = 0; q < 4; ++q) {
                int row = wn * 64 + q * 16 + la;
                uint32_t addr = sB + row * 128 + ((seg ^ (row & 7)) << 4);
                uint32_t r0, r1, r2, r3;
                ldsm_x4(addr, r0, r1, r2, r3);
                bf[2 * q][0] = r0;     bf[2 * q][1] = r2;
                bf[2 * q + 1][0] = r1; bf[2 * q + 1][1] = r3;
            }
            // per mt: load its A frag, then immediately issue its 8 MMAs
            #pragma unroll
            for (int mt = 0; mt < 4; ++mt) {
                int row = wm * 64 + mt * 16 + la;
                uint32_t addr = sa + row * 128 + ((seg ^ (row & 7)) << 4);
                uint32_t af[4];
                ldsm_x4(addr, af[0], af[1], af[2], af[3]);
                #pragma unroll
                for (int nb = 0; nb < 8; ++nb)
                    mma_16816(acc[mt][nb], af, bf[nb][0], bf[nb][1]);
            }
        }
        CP_COMMIT();

        cons = (cons == STAGES - 1) ? 0 : cons + 1;
        prod = (prod == STAGES - 1) ? 0 : prod + 1;
    }

    // ---------------- epilogue: bias + store ----------------
    float2 bv[8];
    #pragma unroll
    for (int nb = 0; nb < 8; ++nb) {
        int col = n0 + wn * 64 + nb * 8 + (lane & 3) * 2;
        bv[nb] = *reinterpret_cast<const float2*>(bias + col);
    }
    #pragma unroll
    for (int mt = 0; mt < 4; ++mt) {
        int gr = m0 + wm * 64 + mt * 16 + (lane >> 2);
        float* r0p = out + (size_t)gr * NDIM;
        float* r1p = r0p + 8 * (size_t)NDIM;
        #pragma unroll
        for (int nb = 0; nb < 8; ++nb) {
            int col = n0 + wn * 64 + nb * 8 + (lane & 3) * 2;
            float2 v0 = make_float2(acc[mt][nb][0] + bv[nb].x,
                                    acc[mt][nb][1] + bv[nb].y);
            float2 v1 = make_float2(acc[mt][nb][2] + bv[nb].x,
                                    acc[mt][nb][3] + bv[nb].y);
            *reinterpret_cast<float2*>(r0p + col) = v0;
            *reinterpret_cast<float2*>(r1p + col) = v1;
        }
    }
}

// ---------------- launch ----------------
extern "C" void kernel_launch(void* const* d_in, const int* in_sizes, int n_in,
                              void* d_out, int out_size) {
    const float* x    = (const float*)d_in[0];
    const float* w    = (const float*)d_in[1];
    const float* bias = (const float*)d_in[2];
    float* out = (float*)d_out;

    conv_x_kernel<<<(BATCH * (size_t)KDIM / 4) / 256, 256>>>((const float4*)x);
    conv_transpose_w_kernel<<<dim3(NDIM / 32, KDIM / 32), dim3(32, 8)>>>(w);

    cudaFuncSetAttribute(gemm_fp16_kernel,
                         cudaFuncAttributeMaxDynamicSharedMemorySize, SMEM_TOTAL);
    gemm_fp16_kernel<<<dim3(NDIM / TN, BATCH / TM), THREADS, SMEM_TOTAL>>>(bias, out);
}

// round 7
// speedup vs baseline: 1.1664x; 1.0501x over previous
#include <cuda_runtime.h>
#include <cuda_fp16.h>
#include <cstdint>

// out[B,N] = x[B,K] @ w[K,N] + bias[N]
// fp16 HMMA m16n8k16 f32-accum. CTA 128x128, 4 warps (2x2), warp tile 64x64,
// 2 CTAs/SM. Register double-buffered ldmatrix fragments (software pipeline).
#define BATCH 4096
#define KDIM  4096
#define NDIM  4096

#define TM 128
#define TN 128
#define KC 64          // K elements per stage (128 bytes fp16 per row)
#define STAGES 3
#define THREADS 128    // 4 warps: 2 (M) x 2 (N), warp tile 64x64
#define K_ITERS (KDIM / KC)   // 64

// ---------------- scratch (device globals: allocation-free) ----------------
__device__ __half g_x[(size_t)BATCH * KDIM];
__device__ __half g_w[(size_t)NDIM * KDIM];   // transposed: [n][k]

// SMEM stage: A tile 128 rows x 128B, B tile 128 rows x 128B
#define STAGE_BYTES ((TM + TN) * 128)       // 32768
#define SMEM_TOTAL  (STAGES * STAGE_BYTES)  // 98304 (x2 CTAs = 192KB/SM)

__device__ __forceinline__ uint32_t smem_u32(const void* p) {
    uint32_t a;
    asm("{ .reg .u64 t; cvta.to.shared.u64 t, %1; cvt.u32.u64 %0, t; }"
        : "=r"(a) : "l"(p));
    return a;
}

__device__ __forceinline__ void cp_async16(uint32_t smaddr, const void* gptr) {
    asm volatile("cp.async.cg.shared.global [%0], [%1], 16;\n"
                 :: "r"(smaddr), "l"(gptr));
}
#define CP_COMMIT() asm volatile("cp.async.commit_group;\n" ::: "memory")
#define CP_WAIT1()  asm volatile("cp.async.wait_group 1;\n" ::: "memory")

__device__ __forceinline__ void ldsm_x4(uint32_t addr, uint32_t& r0, uint32_t& r1,
                                        uint32_t& r2, uint32_t& r3) {
    asm volatile("ldmatrix.sync.aligned.m8n8.x4.shared.b16 {%0,%1,%2,%3}, [%4];"
                 : "=r"(r0), "=r"(r1), "=r"(r2), "=r"(r3) : "r"(addr));
}

__device__ __forceinline__ void mma_16816(float* c, const uint32_t* a,
                                          uint32_t b0, uint32_t b1) {
    asm volatile(
        "mma.sync.aligned.m16n8k16.row.col.f32.f16.f16.f32 "
        "{%0,%1,%2,%3}, {%4,%5,%6,%7}, {%8,%9}, {%0,%1,%2,%3};"
        : "+f"(c[0]), "+f"(c[1]), "+f"(c[2]), "+f"(c[3])
        : "r"(a[0]), "r"(a[1]), "r"(a[2]), "r"(a[3]), "r"(b0), "r"(b1));
}

// ---------------- prepass 1: convert x -> fp16 ----------------
__global__ void __launch_bounds__(256) conv_x_kernel(const float4* __restrict__ x) {
    size_t i = (size_t)blockIdx.x * blockDim.x + threadIdx.x;  // 4 floats / thread
    float4 v = x[i];
    __half2* xp = reinterpret_cast<__half2*>(g_x);
    xp[2 * i]     = __floats2half2_rn(v.x, v.y);
    xp[2 * i + 1] = __floats2half2_rn(v.z, v.w);
}

// ---------------- prepass 2: transpose + convert w -> [n][k] fp16 ----------
__global__ void __launch_bounds__(256) conv_transpose_w_kernel(const float* __restrict__ w) {
    __shared__ float tile[32][33];
    int o0 = blockIdx.x * 32;  // output (N) tile
    int i0 = blockIdx.y * 32;  // input (K) tile
    int tx = threadIdx.x, ty = threadIdx.y;
    #pragma unroll
    for (int r = ty; r < 32; r += 8)
        tile[r][tx] = w[(size_t)(i0 + r) * NDIM + o0 + tx];
    __syncthreads();
    #pragma unroll
    for (int r = ty; r < 32; r += 8) {
        float f = tile[tx][r];  // = w[i0+tx][o0+r]
        g_w[(size_t)(o0 + r) * KDIM + i0 + tx] = __float2half_rn(f);
    }
}

// ---------------- main GEMM ----------------
__global__ void __launch_bounds__(THREADS, 2)
gemm_fp16_kernel(const float* __restrict__ bias, float* __restrict__ out) {
    extern __shared__ char smem[];
    uint32_t sb = smem_u32(smem);
    int tid = threadIdx.x;
    int lane = tid & 31;
    int wid = tid >> 5;
    int wm = wid & 1;       // M warp group: 64 rows
    int wn = wid >> 1;      // N warp group: 64 cols
    int m0 = blockIdx.y * TM;
    int n0 = blockIdx.x * TN;

    float acc[4][8][4];     // [mt m16 tile][nb n8 tile][c0..c3]
    #pragma unroll
    for (int i = 0; i < 4; ++i)
        #pragma unroll
        for (int j = 0; j < 8; ++j)
            #pragma unroll
            for (int k = 0; k < 4; ++k) acc[i][j][k] = 0.f;

    // --- producer setup: per-thread fixed (row,seg); advance k per stage ---
    // 2048 cp.async per stage; 16 per thread. j<8 -> A rows, j>=8 -> B rows.
    int prow = tid >> 3;          // 0..15
    int pseg = tid & 7;
    const __half* pA = g_x + (size_t)(m0 + prow) * KDIM + pseg * 8;
    const __half* pB = g_w + (size_t)(n0 + prow) * KDIM + pseg * 8;
    // smem offsets (stage-relative), fixed per thread per j
    uint32_t soA[8], soB[8];
    #pragma unroll
    for (int j = 0; j < 8; ++j) {
        int rowA = prow + j * 16;
        soA[j] = rowA * 128 + ((pseg ^ (rowA & 7)) << 4);
        soB[j] = TM * 128 + rowA * 128 + ((pseg ^ (rowA & 7)) << 4);
    }

    #define LOAD_STAGE_PART(sa_, kk_, j0_, j1_)                                   \
        _Pragma("unroll")                                                          \
        for (int j = (j0_); j < (j1_); ++j) {                                      \
            if (j < 8) cp_async16((sa_) + soA[j], pA + (size_t)j * 16 * KDIM + (kk_)); \
            else       cp_async16((sa_) + soB[j - 8], pB + (size_t)(j - 8) * 16 * KDIM + (kk_)); \
        }

    // prologue: stages 0 and 1
    LOAD_STAGE_PART(sb + 0 * STAGE_BYTES, 0 * KC, 0, 16); CP_COMMIT();
    LOAD_STAGE_PART(sb + 1 * STAGE_BYTES, 1 * KC, 0, 16); CP_COMMIT();

    int la = (lane & 15);
    int khalf = lane >> 4;

    // fragment double buffers
    uint32_t afb[2][4][4];
    uint32_t bfb[2][8][2];

    #define LOAD_FRAGS(sa_, sB_, ks_, buf_) do {                                  \
        int seg_ = 2 * (ks_) + khalf;                                             \
        _Pragma("unroll")                                                          \
        for (int q = 0; q < 4; ++q) {                                             \
            int row_ = wn * 64 + q * 16 + la;                                     \
            uint32_t addr_ = (sB_) + row_ * 128 + ((seg_ ^ (row_ & 7)) << 4);     \
            uint32_t r0_, r1_, r2_, r3_;                                          \
            ldsm_x4(addr_, r0_, r1_, r2_, r3_);                                   \
            bfb[buf_][2 * q][0] = r0_;     bfb[buf_][2 * q][1] = r2_;             \
            bfb[buf_][2 * q + 1][0] = r1_; bfb[buf_][2 * q + 1][1] = r3_;         \
        }                                                                          \
        _Pragma("unroll")                                                          \
        for (int mt = 0; mt < 4; ++mt) {                                          \
            int row_ = wm * 64 + mt * 16 + la;                                    \
            uint32_t addr_ = (sa_) + row_ * 128 + ((seg_ ^ (row_ & 7)) << 4);     \
            ldsm_x4(addr_, afb[buf_][mt][0], afb[buf_][mt][1],                    \
                    afb[buf_][mt][2], afb[buf_][mt][3]);                          \
        }                                                                          \
    } while (0)

    int cons = 0, prod = 2;   // stage indices
    for (int it = 0; it < K_ITERS; ++it) {
        CP_WAIT1();
        __syncthreads();

        uint32_t sa = sb + cons * STAGE_BYTES;
        uint32_t sB = sa + TM * 128;
        uint32_t sp = sb + prod * STAGE_BYTES;
        bool do_load = (it + 2 < K_ITERS);
        int kp = (it + 2) * KC;

        LOAD_FRAGS(sa, sB, 0, 0);

        #pragma unroll
        for (int ks = 0; ks < 4; ++ks) {
            int buf = ks & 1;
            // prefetch next ks fragments before this ks's MMAs
            if (ks < 3) LOAD_FRAGS(sa, sB, ks + 1, buf ^ 1);
            // spread producer cp.async: 4 per thread per ks
            if (do_load) LOAD_STAGE_PART(sp, kp, ks * 4, ks * 4 + 4);
            #pragma unroll
            for (int mt = 0; mt < 4; ++mt)
                #pragma unroll
                for (int nb = 0; nb < 8; ++nb)
                    mma_16816(acc[mt][nb], afb[buf][mt],
                              bfb[buf][nb][0], bfb[buf][nb][1]);
        }
        CP_COMMIT();

        cons = (cons == STAGES - 1) ? 0 : cons + 1;
        prod = (prod == STAGES - 1) ? 0 : prod + 1;
    }

    // ---------------- epilogue: bias + store ----------------
    float2 bv[8];
    #pragma unroll
    for (int nb = 0; nb < 8; ++nb) {
        int col = n0 + wn * 64 + nb * 8 + (lane & 3) * 2;
        bv[nb] = *reinterpret_cast<const float2*>(bias + col);
    }
    #pragma unroll
    for (int mt = 0; mt < 4; ++mt) {
        int gr = m0 + wm * 64 + mt * 16 + (lane >> 2);
        float* r0p = out + (size_t)gr * NDIM;
        float* r1p = r0p + 8 * (size_t)NDIM;
        #pragma unroll
        for (int nb = 0; nb < 8; ++nb) {
            int col = n0 + wn * 64 + nb * 8 + (lane & 3) * 2;
            float2 v0 = make_float2(acc[mt][nb][0] + bv[nb].x,
                                    acc[mt][nb][1] + bv[nb].y);
            float2 v1 = make_float2(acc[mt][nb][2] + bv[nb].x,
                                    acc[mt][nb][3] + bv[nb].y);
            *reinterpret_cast<float2*>(r0p + col) = v0;
            *reinterpret_cast<float2*>(r1p + col) = v1;
        }
    }
}

// ---------------- launch ----------------
extern "C" void kernel_launch(void* const* d_in, const int* in_sizes, int n_in,
                              void* d_out, int out_size) {
    const float* x    = (const float*)d_in[0];
    const float* w    = (const float*)d_in[1];
    const float* bias = (const float*)d_in[2];
    float* out = (float*)d_out;

    conv_x_kernel<<<(BATCH * (size_t)KDIM / 4) / 256, 256>>>((const float4*)x);
    conv_transpose_w_kernel<<<dim3(NDIM / 32, KDIM / 32), dim3(32, 8)>>>(w);

    cudaFuncSetAttribute(gemm_fp16_kernel,
                         cudaFuncAttributeMaxDynamicSharedMemorySize, SMEM_TOTAL);
    gemm_fp16_kernel<<<dim3(NDIM / TN, BATCH / TM), THREADS, SMEM_TOTAL>>>(bias, out);
}